// round 17
// baseline (speedup 1.0000x reference)
#include <cuda_runtime.h>
#include <cuda_bf16.h>
#include <math.h>
#include <stdint.h>

// Problem constants
#define BATCH 8
#define LSEQ  1024
#define DMODEL 1024
#define NHEAD 16
#define DK 64

// ---------------------------------------------------------------------------
// Scratch (__device__ globals)
//   g_f32 : QS[8M] KS[8M] VS[8M] CTX[8M] floats
//   g_wbf : WQh WQl WKh WKl WVh WVl WPh WPl (1M bf16 each)  [N,K] row-major
//           + VTh[8M] VTl[8M]  (V transposed per (h,b): [z][n=64][k=1024])
// ---------------------------------------------------------------------------
#define M1 (1024u*1024u)
__device__ float          g_f32[(size_t)32 * M1];
__device__ __nv_bfloat16  g_wbf[(size_t)24 * M1];

// ======================= helpers ===========================================
__device__ __forceinline__ uint32_t smem_u32(const void* p) {
    uint32_t a;
    asm("{ .reg .u64 t; cvta.to.shared.u64 t, %1; cvt.u32.u64 %0, t; }"
        : "=r"(a) : "l"(p));
    return a;
}
__device__ __forceinline__ void ldsm4(uint32_t* r, uint32_t addr) {
    asm volatile("ldmatrix.sync.aligned.m8n8.x4.shared.b16 {%0,%1,%2,%3}, [%4];"
                 : "=r"(r[0]), "=r"(r[1]), "=r"(r[2]), "=r"(r[3]) : "r"(addr));
}
__device__ __forceinline__ void mma16816(float* d, const uint32_t* a, const uint32_t* b) {
    asm volatile(
        "mma.sync.aligned.m16n8k16.row.col.f32.bf16.bf16.f32 "
        "{%0,%1,%2,%3}, {%4,%5,%6,%7}, {%8,%9}, {%0,%1,%2,%3};"
        : "+f"(d[0]), "+f"(d[1]), "+f"(d[2]), "+f"(d[3])
        : "r"(a[0]), "r"(a[1]), "r"(a[2]), "r"(a[3]), "r"(b[0]), "r"(b[1]));
}
__device__ __forceinline__ void split4(float4 v, uint32_t& h0, uint32_t& h1,
                                       uint32_t& l0, uint32_t& l1) {
    __nv_bfloat162 ha = __floats2bfloat162_rn(v.x, v.y);
    __nv_bfloat162 hb = __floats2bfloat162_rn(v.z, v.w);
    float lx = v.x - __bfloat162float(ha.x);
    float ly = v.y - __bfloat162float(ha.y);
    float lz = v.z - __bfloat162float(hb.x);
    float lw = v.w - __bfloat162float(hb.y);
    __nv_bfloat162 la = __floats2bfloat162_rn(lx, ly);
    __nv_bfloat162 lb = __floats2bfloat162_rn(lz, lw);
    h0 = (uint32_t)__bfloat16_as_ushort(ha.x) | ((uint32_t)__bfloat16_as_ushort(ha.y) << 16);
    h1 = (uint32_t)__bfloat16_as_ushort(hb.x) | ((uint32_t)__bfloat16_as_ushort(hb.y) << 16);
    l0 = (uint32_t)__bfloat16_as_ushort(la.x) | ((uint32_t)__bfloat16_as_ushort(la.y) << 16);
    l1 = (uint32_t)__bfloat16_as_ushort(lb.x) | ((uint32_t)__bfloat16_as_ushort(lb.y) << 16);
}

// ======================= weight prep kernels ================================
__global__ void reshape_split_qkv(const float* __restrict__ w,
                                  __nv_bfloat16* __restrict__ hi,
                                  __nv_bfloat16* __restrict__ lo) {
    int i = blockIdx.x * 256 + threadIdx.x;   // 1M
    int n = i >> 10;
    int d = i & 1023;
    float v = w[((n >> 6) << 16) + (d << 6) + (n & 63)];
    __nv_bfloat16 h = __float2bfloat16(v);
    hi[i] = h;
    lo[i] = __float2bfloat16(v - __bfloat162float(h));
}
__global__ void split_bf16_kernel(const float4* __restrict__ x,
                                  uint2* __restrict__ hi, uint2* __restrict__ lo, int n4) {
    int i = blockIdx.x * 256 + threadIdx.x;
    if (i >= n4) return;
    uint32_t h0, h1, l0, l1;
    split4(x[i], h0, h1, l0, l1);
    hi[i] = make_uint2(h0, h1);
    lo[i] = make_uint2(l0, l1);
}

// VS fp32 [b*1024+k][h*64+n]  ->  VT bf16 hi/lo [(h*8+b)*64+n][k]
__global__ void vtrans_kernel(const float* __restrict__ vs,
                              __nv_bfloat16* __restrict__ vth,
                              __nv_bfloat16* __restrict__ vtl) {
    __shared__ float tile[32][33];
    const int k0 = blockIdx.x * 32;
    const int n0 = blockIdx.y * 32;
    const int z  = blockIdx.z;         // h*8+b
    const int h = z >> 3, b = z & 7;
    const int tx = threadIdx.x, ty = threadIdx.y;   // (32,8)
    for (int r = ty; r < 32; r += 8)
        tile[r][tx] = vs[(size_t)(b * 1024 + k0 + r) * 1024 + h * 64 + n0 + tx];
    __syncthreads();
    for (int r = ty; r < 32; r += 8) {
        float v = tile[tx][r];
        __nv_bfloat16 hv = __float2bfloat16(v);
        size_t o = (size_t)(z * 64 + n0 + r) * 1024 + k0 + tx;
        vth[o] = hv;
        vtl[o] = __float2bfloat16(v - __bfloat162float(hv));
    }
}

// ======================= mma.sync split-bf16 GEMM (projections) =============
#define GSTRIDE 80
#define TILE_B  (128 * GSTRIDE)
#define STAGE_B (4 * TILE_B)
#define GEMM_SMEM (2 * STAGE_B)

struct GemmBatch {
    const float* A[3];
    const __nv_bfloat16* Bh[3];
    const __nv_bfloat16* Bl[3];
    float* C[3];
};

template <int EPI>
__global__ __launch_bounds__(256, 1)
void gemm_mma_kernel(GemmBatch p, const float* __restrict__ bias,
                     const float* __restrict__ resid) {
    extern __shared__ __align__(128) char sm[];
    const int t = threadIdx.x;
    const int bx = blockIdx.x, by = blockIdx.y, bz = blockIdx.z;
    const int wid = t >> 5, lane = t & 31;

    const float* Abase = p.A[bz] + (size_t)(by * 128) * 1024;
    const __nv_bfloat16* Bhb = p.Bh[bz] + (size_t)(bx * 128) * 1024;
    const __nv_bfloat16* Blb = p.Bl[bz] + (size_t)(bx * 128) * 1024;
    float* C = p.C[bz];

    float4 ar[4];
    uint4  bhr[2], blr[2];

    const uint32_t smb = smem_u32(sm);
    const int wm = wid & 3;
    const int wn = wid >> 2;

    float acc[2][8][4];
#pragma unroll
    for (int mt = 0; mt < 2; mt++)
#pragma unroll
        for (int nt = 0; nt < 8; nt++)
#pragma unroll
            for (int j = 0; j < 4; j++) acc[mt][nt][j] = 0.0f;

    const uint32_t aoff = (uint32_t)((wm * 32 + (lane & 15)) * GSTRIDE + (lane >> 4) * 16);
    const uint32_t boff = (uint32_t)((wn * 64 + (lane & 7) + ((lane >> 4) & 1) * 8) * GSTRIDE
                                     + ((lane >> 3) & 1) * 16);

#define LOAD_REGS(k0)                                                         \
    {                                                                         \
        _Pragma("unroll")                                                     \
        for (int i = 0; i < 4; i++) {                                         \
            int idx = t + 256 * i, row = idx >> 3, seg = idx & 7;             \
            ar[i] = *(const float4*)(Abase + (size_t)row * 1024 + (k0) + seg * 4); \
        }                                                                     \
        _Pragma("unroll")                                                     \
        for (int i = 0; i < 2; i++) {                                         \
            int idx = t + 256 * i, row = idx >> 2, seg = idx & 3;             \
            const char* ph = (const char*)(Bhb + (size_t)row * 1024 + (k0)) + seg * 16; \
            const char* pl = (const char*)(Blb + (size_t)row * 1024 + (k0)) + seg * 16; \
            bhr[i] = *(const uint4*)ph;                                       \
            blr[i] = *(const uint4*)pl;                                       \
        }                                                                     \
    }

#define STORE_SMEM(buf)                                                      \
    {                                                                         \
        char* AH = sm + (buf) * STAGE_B;                                      \
        char* AL = AH + TILE_B;                                               \
        char* BHs = AH + 2 * TILE_B;                                          \
        char* BLs = AH + 3 * TILE_B;                                          \
        _Pragma("unroll")                                                     \
        for (int i = 0; i < 4; i++) {                                         \
            int idx = t + 256 * i, row = idx >> 3, seg = idx & 7;             \
            uint32_t h0, h1, l0, l1;                                          \
            split4(ar[i], h0, h1, l0, l1);                                    \
            *(uint2*)(AH + row * GSTRIDE + seg * 8) = make_uint2(h0, h1);     \
            *(uint2*)(AL + row * GSTRIDE + seg * 8) = make_uint2(l0, l1);     \
        }                                                                     \
        _Pragma("unroll")                                                     \
        for (int i = 0; i < 2; i++) {                                         \
            int idx = t + 256 * i, row = idx >> 2, seg = idx & 3;             \
            *(uint4*)(BHs + row * GSTRIDE + seg * 16) = bhr[i];               \
            *(uint4*)(BLs + row * GSTRIDE + seg * 16) = blr[i];               \
        }                                                                     \
    }

    LOAD_REGS(0);
    STORE_SMEM(0);
    __syncthreads();

    for (int c = 0; c < 32; c++) {
        const int buf = c & 1;
        if (c + 1 < 32) LOAD_REGS((c + 1) * 32);

        const uint32_t AHb = smb + buf * STAGE_B;
        const uint32_t ALb = AHb + TILE_B;
        const uint32_t BHt = AHb + 2 * TILE_B;
        const uint32_t BLt = AHb + 3 * TILE_B;
#pragma unroll
        for (int ks = 0; ks < 2; ks++) {
            const uint32_t kb = ks * 32;
            uint32_t ah[2][4], al[2][4], bh[8][2], bl[8][2];
#pragma unroll
            for (int mt = 0; mt < 2; mt++) {
                ldsm4(ah[mt], AHb + aoff + mt * 16 * GSTRIDE + kb);
                ldsm4(al[mt], ALb + aoff + mt * 16 * GSTRIDE + kb);
            }
#pragma unroll
            for (int pg = 0; pg < 4; pg++) {
                uint32_t r[4];
                ldsm4(r, BHt + boff + pg * 16 * GSTRIDE + kb);
                bh[2 * pg][0] = r[0]; bh[2 * pg][1] = r[1];
                bh[2 * pg + 1][0] = r[2]; bh[2 * pg + 1][1] = r[3];
                ldsm4(r, BLt + boff + pg * 16 * GSTRIDE + kb);
                bl[2 * pg][0] = r[0]; bl[2 * pg][1] = r[1];
                bl[2 * pg + 1][0] = r[2]; bl[2 * pg + 1][1] = r[3];
            }
#pragma unroll
            for (int mt = 0; mt < 2; mt++)
#pragma unroll
                for (int nt = 0; nt < 8; nt++) {
                    mma16816(acc[mt][nt], ah[mt], bh[nt]);
                    mma16816(acc[mt][nt], ah[mt], bl[nt]);
                    mma16816(acc[mt][nt], al[mt], bh[nt]);
                }
        }
        if (c + 1 < 32) {
            STORE_SMEM(buf ^ 1);
            __syncthreads();
        }
    }

    const int r0 = lane >> 2, c0 = (lane & 3) * 2;
#pragma unroll
    for (int mt = 0; mt < 2; mt++)
#pragma unroll
        for (int nt = 0; nt < 8; nt++)
#pragma unroll
            for (int half = 0; half < 2; half++) {
                int row = by * 128 + wm * 32 + mt * 16 + r0 + half * 8;
                int col = bx * 128 + wn * 64 + nt * 8 + c0;
                float2 v = make_float2(acc[mt][nt][half * 2], acc[mt][nt][half * 2 + 1]);
                size_t idx = (size_t)row * 1024 + col;
                if (EPI) {
                    v.x += bias[col]     + resid[idx];
                    v.y += bias[col + 1] + resid[idx + 1];
                }
                *(float2*)(C + idx) = v;
            }
#undef LOAD_REGS
#undef STORE_SMEM
}

// ======================= fused attention ====================================
// One CTA per (z = h*8+b, 32-query-row block). 256 threads.
// Phase 1: S = QK^T/32 via split-bf16 mma, streaming 128-key chunks -> S smem
// Phase 2: mask + softmax in smem, attn written to HBM once
// Phase 3: O = P V via mma (P converted to bf16 hi/lo per chunk, V from VT)
#define S_OFF   0
#define QH_OFF  131072
#define QL_OFF  135680
#define KH_OFF  140288
#define KL_OFF  158720
#define VH_OFF  140288
#define VL_OFF  157696
#define PH_OFF  175104
#define PL_OFF  183808
#define AT_SMEM 192512

__global__ __launch_bounds__(256, 1)
void attn_fused_kernel(const float* __restrict__ qs, const float* __restrict__ ks,
                       const __nv_bfloat16* __restrict__ VTh,
                       const __nv_bfloat16* __restrict__ VTl,
                       const unsigned char* __restrict__ mask,
                       float* __restrict__ attn_out, float* __restrict__ ctx) {
    extern __shared__ __align__(128) char sm[];
    const int t = threadIdx.x, wid = t >> 5, lane = t & 31;
    const int q0 = blockIdx.x * 32;
    const int z = blockIdx.y;                 // h*8+b
    const int h = z >> 3, b = z & 7;
    const uint32_t smb = smem_u32(sm);
    const int r0 = lane >> 2, c0 = (lane & 3) * 2;
    float* S = (float*)sm;

    // ---- load Q tile (32x64 fp32 -> hi/lo bf16 smem) ----
    {
        const float* Qg = qs + (size_t)(b * 1024 + q0) * 1024 + h * 64;
#pragma unroll
        for (int i = 0; i < 2; i++) {
            int idx = t + 256 * i, row = idx >> 4, seg = idx & 15;
            float4 v = *(const float4*)(Qg + (size_t)row * 1024 + seg * 4);
            uint32_t h0, h1, l0, l1;
            split4(v, h0, h1, l0, l1);
            *(uint2*)(sm + QH_OFF + row * 144 + seg * 8) = make_uint2(h0, h1);
            *(uint2*)(sm + QL_OFF + row * 144 + seg * 8) = make_uint2(l0, l1);
        }
    }

    // ---- Phase 1: QK^T ----
    {
        const uint32_t QHa = smb + QH_OFF, QLa = smb + QL_OFF;
        const uint32_t KHa = smb + KH_OFF, KLa = smb + KL_OFF;
        const uint32_t aoffQ = (uint32_t)((lane & 15) * 144 + (lane >> 4) * 16);
        const uint32_t boffK = (uint32_t)((wid * 16 + (lane & 7) + ((lane >> 4) & 1) * 8) * 144
                                          + ((lane >> 3) & 1) * 16);
        const float scale = 1.0f / 32.0f;

        for (int kc = 0; kc < 8; kc++) {
            __syncthreads();     // Q ready (first iter) / previous mma done with K buf
            const float* Kg = ks + (size_t)(b * 1024 + kc * 128) * 1024 + h * 64;
#pragma unroll
            for (int i = 0; i < 8; i++) {
                int idx = t + 256 * i, row = idx >> 4, seg = idx & 15;
                float4 v = *(const float4*)(Kg + (size_t)row * 1024 + seg * 4);
                uint32_t h0, h1, l0, l1;
                split4(v, h0, h1, l0, l1);
                *(uint2*)(sm + KH_OFF + row * 144 + seg * 8) = make_uint2(h0, h1);
                *(uint2*)(sm + KL_OFF + row * 144 + seg * 8) = make_uint2(l0, l1);
            }
            __syncthreads();

            float acc[2][2][4] = {};
#pragma unroll
            for (int ksd = 0; ksd < 4; ksd++) {
                const uint32_t kb = ksd * 32;
                uint32_t ah[2][4], al[2][4], bh[2][2], bl[2][2];
#pragma unroll
                for (int mt = 0; mt < 2; mt++) {
                    ldsm4(ah[mt], QHa + aoffQ + mt * 16 * 144 + kb);
                    ldsm4(al[mt], QLa + aoffQ + mt * 16 * 144 + kb);
                }
                {
                    uint32_t r[4];
                    ldsm4(r, KHa + boffK + kb);
                    bh[0][0] = r[0]; bh[0][1] = r[1]; bh[1][0] = r[2]; bh[1][1] = r[3];
                    ldsm4(r, KLa + boffK + kb);
                    bl[0][0] = r[0]; bl[0][1] = r[1]; bl[1][0] = r[2]; bl[1][1] = r[3];
                }
#pragma unroll
                for (int mt = 0; mt < 2; mt++)
#pragma unroll
                    for (int nt = 0; nt < 2; nt++) {
                        mma16816(acc[mt][nt], ah[mt], bh[nt]);
                        mma16816(acc[mt][nt], ah[mt], bl[nt]);
                        mma16816(acc[mt][nt], al[mt], bh[nt]);
                    }
            }
#pragma unroll
            for (int mt = 0; mt < 2; mt++)
#pragma unroll
                for (int nt = 0; nt < 2; nt++)
#pragma unroll
                    for (int half = 0; half < 2; half++) {
                        int row = mt * 16 + r0 + half * 8;
                        int col = kc * 128 + wid * 16 + nt * 8 + c0;
                        *(float2*)(S + row * 1024 + col) =
                            make_float2(acc[mt][nt][half * 2] * scale,
                                        acc[mt][nt][half * 2 + 1] * scale);
                    }
        }
    }
    __syncthreads();

    // ---- Phase 2: mask + softmax (warp w owns rows 4w..4w+3), write attn ----
    {
        const float NEG_INF = __int_as_float(0xff800000);
#pragma unroll
        for (int i = 0; i < 4; i++) {
            int r = wid * 4 + i;
            float4* srow = (float4*)(S + r * 1024);
            const uchar4* mr = (const uchar4*)(mask + (size_t)(b * 1024 + q0 + r) * 1024);
            float4 v[8];
            float m = NEG_INF;
#pragma unroll
            for (int j = 0; j < 8; j++) {
                v[j] = srow[lane + j * 32];
                uchar4 mm = mr[lane + j * 32];
                if (mm.x) v[j].x = NEG_INF;
                if (mm.y) v[j].y = NEG_INF;
                if (mm.z) v[j].z = NEG_INF;
                if (mm.w) v[j].w = NEG_INF;
                m = fmaxf(m, fmaxf(fmaxf(v[j].x, v[j].y), fmaxf(v[j].z, v[j].w)));
            }
#pragma unroll
            for (int o = 16; o > 0; o >>= 1) m = fmaxf(m, __shfl_xor_sync(0xffffffffu, m, o));
            float s = 0.0f;
#pragma unroll
            for (int j = 0; j < 8; j++) {
                v[j].x = __expf(v[j].x - m);
                v[j].y = __expf(v[j].y - m);
                v[j].z = __expf(v[j].z - m);
                v[j].w = __expf(v[j].w - m);
                s += v[j].x + v[j].y + v[j].z + v[j].w;
            }
#pragma unroll
            for (int o = 16; o > 0; o >>= 1) s += __shfl_xor_sync(0xffffffffu, s, o);
            const float inv = 1.0f / s;
            float4* arow = (float4*)(attn_out + ((size_t)z * 1024 + q0 + r) * 1024);
#pragma unroll
            for (int j = 0; j < 8; j++) {
                v[j].x *= inv; v[j].y *= inv; v[j].z *= inv; v[j].w *= inv;
                srow[lane + j * 32] = v[j];
                arow[lane + j * 32] = v[j];
            }
        }
    }

    // ---- Phase 3: O = P V ----
    {
        const uint32_t VHa = smb + VH_OFF, VLa = smb + VL_OFF;
        const uint32_t PHa = smb + PH_OFF, PLa = smb + PL_OFF;
        const uint32_t aoffP = (uint32_t)((lane & 15) * 272 + (lane >> 4) * 16);
        const uint32_t boffV = (uint32_t)((wid * 8 + (lane & 7)) * 272
                                          + ((lane >> 3) & 1) * 16 + (lane >> 4) * 32);
        const __nv_bfloat16* Vhg = VTh + (size_t)z * 64 * 1024;
        const __nv_bfloat16* Vlg = VTl + (size_t)z * 64 * 1024;

        float pacc[2][4] = {};
        for (int kc = 0; kc < 8; kc++) {
            __syncthreads();   // softmax done (first iter) / previous mma done with bufs
            // convert P chunk 32x128 fp32 -> hi/lo bf16
#pragma unroll
            for (int i = 0; i < 4; i++) {
                int idx = t + 256 * i, row = idx >> 5, seg = idx & 31;
                float4 v = *(const float4*)(S + row * 1024 + kc * 128 + seg * 4);
                uint32_t h0, h1, l0, l1;
                split4(v, h0, h1, l0, l1);
                *(uint2*)(sm + PH_OFF + row * 272 + seg * 8) = make_uint2(h0, h1);
                *(uint2*)(sm + PL_OFF + row * 272 + seg * 8) = make_uint2(l0, l1);
            }
            // load V chunk 64n x 128k (bf16 hi/lo): 64 rows x 16 segs of 16B
#pragma unroll
            for (int i = 0; i < 4; i++) {
                int idx = t + 256 * i, row = idx >> 4, seg = idx & 15;
                const char* ph = (const char*)(Vhg + (size_t)row * 1024 + kc * 128) + seg * 16;
                const char* pl = (const char*)(Vlg + (size_t)row * 1024 + kc * 128) + seg * 16;
                *(uint4*)(sm + VH_OFF + row * 272 + seg * 16) = *(const uint4*)ph;
                *(uint4*)(sm + VL_OFF + row * 272 + seg * 16) = *(const uint4*)pl;
            }
            __syncthreads();

#pragma unroll
            for (int k2 = 0; k2 < 4; k2++) {
                const uint32_t kb = k2 * 64;
                uint32_t bhv[4], blv[4];
                ldsm4(bhv, VHa + boffV + kb);
                ldsm4(blv, VLa + boffV + kb);
#pragma unroll
                for (int kk = 0; kk < 2; kk++) {
                    uint32_t ph_[2][4], pl_[2][4];
#pragma unroll
                    for (int mt = 0; mt < 2; mt++) {
                        ldsm4(ph_[mt], PHa + aoffP + mt * 16 * 272 + kb + kk * 32);
                        ldsm4(pl_[mt], PLa + aoffP + mt * 16 * 272 + kb + kk * 32);
                    }
#pragma unroll
                    for (int mt = 0; mt < 2; mt++) {
                        mma16816(pacc[mt], ph_[mt], &bhv[kk * 2]);
                        mma16816(pacc[mt], ph_[mt], &blv[kk * 2]);
                        mma16816(pacc[mt], pl_[mt], &bhv[kk * 2]);
                    }
                }
            }
        }
#pragma unroll
        for (int mt = 0; mt < 2; mt++)
#pragma unroll
            for (int half = 0; half < 2; half++) {
                int row = q0 + mt * 16 + r0 + half * 8;
                int col = h * 64 + wid * 8 + c0;
                *(float2*)(ctx + (size_t)(b * 1024 + row) * 1024 + col) =
                    make_float2(pacc[mt][half * 2], pacc[mt][half * 2 + 1]);
            }
    }
}

// ---------------------------------------------------------------------------
// In-place LayerNorm
// ---------------------------------------------------------------------------
__global__ void ln_kernel(float* __restrict__ y,
                          const float* __restrict__ gamma,
                          const float* __restrict__ beta) {
    __shared__ float red[18];
    const int row = blockIdx.x;
    const int t = threadIdx.x;
    float* p = y + (size_t)row * 1024;
    float v[4];
    float s = 0.0f, s2 = 0.0f;
#pragma unroll
    for (int j = 0; j < 4; j++) {
        v[j] = p[t + 256 * j];
        s += v[j];
        s2 += v[j] * v[j];
    }
#pragma unroll
    for (int o = 16; o > 0; o >>= 1) {
        s  += __shfl_xor_sync(0xffffffffu, s, o);
        s2 += __shfl_xor_sync(0xffffffffu, s2, o);
    }
    int warp = t >> 5, lane = t & 31;
    if (lane == 0) { red[warp] = s; red[8 + warp] = s2; }
    __syncthreads();
    if (t == 0) {
        float a = 0.0f, bsum = 0.0f;
#pragma unroll
        for (int w = 0; w < 8; w++) { a += red[w]; bsum += red[8 + w]; }
        red[16] = a; red[17] = bsum;
    }
    __syncthreads();
    float mean = red[16] * (1.0f / 1024.0f);
    float var  = red[17] * (1.0f / 1024.0f) - mean * mean;
    float inv  = rsqrtf(var + 1e-5f);
#pragma unroll
    for (int j = 0; j < 4; j++) {
        int c = t + 256 * j;
        p[c] = (v[j] - mean) * inv * gamma[c] + beta[c];
    }
}

// ---------------------------------------------------------------------------
// kernel_launch
// ---------------------------------------------------------------------------
extern "C" void kernel_launch(void* const* d_in, const int* in_sizes, int n_in,
                              void* d_out, int out_size) {
    const float* q      = (const float*)d_in[0];
    const float* k      = (const float*)d_in[1];
    const float* v      = (const float*)d_in[2];
    const unsigned char* mask = (const unsigned char*)d_in[3];
    const float* w_qs   = (const float*)d_in[4];
    const float* w_ks   = (const float*)d_in[5];
    const float* w_vs   = (const float*)d_in[6];
    const float* proj_w = (const float*)d_in[7];
    const float* proj_b = (const float*)d_in[8];
    const float* gamma  = (const float*)d_in[9];
    const float* beta   = (const float*)d_in[10];

    float* out = (float*)d_out;
    float* attn_out = out + (size_t)8192 * 1024;

    float* F = nullptr;  __nv_bfloat16* WB = nullptr;
    cudaGetSymbolAddress((void**)&F,  g_f32);
    cudaGetSymbolAddress((void**)&WB, g_wbf);

    float* QS  = F;
    float* KS  = F + (size_t)8  * M1;
    float* VS  = F + (size_t)16 * M1;
    float* CTX = F + (size_t)24 * M1;

    __nv_bfloat16* WQh = WB + 0 * M1; __nv_bfloat16* WQl = WB + 1 * M1;
    __nv_bfloat16* WKh = WB + 2 * M1; __nv_bfloat16* WKl = WB + 3 * M1;
    __nv_bfloat16* WVh = WB + 4 * M1; __nv_bfloat16* WVl = WB + 5 * M1;
    __nv_bfloat16* WPh = WB + 6 * M1; __nv_bfloat16* WPl = WB + 7 * M1;
    __nv_bfloat16* VTh = WB + (size_t)8  * M1;
    __nv_bfloat16* VTl = WB + (size_t)16 * M1;

    cudaFuncSetAttribute(gemm_mma_kernel<0>, cudaFuncAttributeMaxDynamicSharedMemorySize, GEMM_SMEM);
    cudaFuncSetAttribute(gemm_mma_kernel<1>, cudaFuncAttributeMaxDynamicSharedMemorySize, GEMM_SMEM);
    cudaFuncSetAttribute(attn_fused_kernel, cudaFuncAttributeMaxDynamicSharedMemorySize, AT_SMEM);

    // weights -> bf16 hi/lo in [N,K] layout
    reshape_split_qkv<<<4096, 256>>>(w_qs, WQh, WQl);
    reshape_split_qkv<<<4096, 256>>>(w_ks, WKh, WKl);
    reshape_split_qkv<<<4096, 256>>>(w_vs, WVh, WVl);
    split_bf16_kernel<<<1024, 256>>>((const float4*)proj_w, (uint2*)WPh, (uint2*)WPl, 256 * 1024);

    // QKV projections: one batched launch (z selects q/k/v)
    GemmBatch qkv;
    qkv.A[0] = q;  qkv.Bh[0] = WQh; qkv.Bl[0] = WQl; qkv.C[0] = QS;
    qkv.A[1] = k;  qkv.Bh[1] = WKh; qkv.Bl[1] = WKl; qkv.C[1] = KS;
    qkv.A[2] = v;  qkv.Bh[2] = WVh; qkv.Bl[2] = WVl; qkv.C[2] = VS;
    gemm_mma_kernel<0><<<dim3(8, 64, 3), 256, GEMM_SMEM>>>(qkv, nullptr, nullptr);

    // V transpose + split for PV
    vtrans_kernel<<<dim3(32, 2, 128), dim3(32, 8)>>>(VS, VTh, VTl);

    // fused attention: QK^T -> softmax -> attn write -> PV
    attn_fused_kernel<<<dim3(32, 128), 256, AT_SMEM>>>(QS, KS, VTh, VTl, mask, attn_out, CTX);

    // output projection + bias + residual, then in-place LayerNorm
    GemmBatch pj;
    pj.A[0] = CTX; pj.Bh[0] = WPh; pj.Bl[0] = WPl; pj.C[0] = out;
    pj.A[1] = pj.A[2] = nullptr; pj.Bh[1] = pj.Bh[2] = nullptr;
    pj.Bl[1] = pj.Bl[2] = nullptr; pj.C[1] = pj.C[2] = nullptr;
    gemm_mma_kernel<1><<<dim3(8, 64, 1), 256, GEMM_SMEM>>>(pj, proj_b, q);
    ln_kernel<<<8192, 256>>>(out, gamma, beta);
}